// round 4
// baseline (speedup 1.0000x reference)
#include <cuda_runtime.h>
#include <cuda_bf16.h>
#include <cstddef>
#include <cstdint>

#define N_LIT 200000
#define N_CLS 800000
#define NE    2400000
#define NT    (N_CLS + N_LIT)
#define CH    64
#define NVAR  (N_LIT/2)
#define NLAY  4
#define SCAN_B 1024
#define NPB   64          // nodes per block in fused kernels
#define ST    130         // smem A-tile stride in floats (bank-safe)

typedef unsigned long long u64;

// ---------------- device scratch (static, no allocation) ----------------
__device__ float g_hlA[(size_t)N_LIT * CH];
__device__ float g_hlB[(size_t)N_LIT * CH];
__device__ float g_hc [(size_t)N_CLS * CH];
__device__ int   g_cnt[NT];          // zero-initialized; re-zeroed by fill_kernel each call
__device__ float g_inv[NT];
__device__ int   g_rs [NT + 1];
__device__ int   g_cur[NT];
__device__ int   g_adj[2 * NE];      // [0,NE): lits grouped by clause; [NE,2NE): clauses by literal
__device__ int   g_bsum[1024];

__device__ __forceinline__ float silu(float x) { return x / (1.0f + __expf(-x)); }

// ---- f32x2 packed helpers (FFMA2 path, sm_100+) ----
__device__ __forceinline__ u64 pack2(float lo, float hi) {
    u64 r; asm("mov.b64 %0, {%1,%2};" : "=l"(r) : "f"(lo), "f"(hi)); return r;
}
__device__ __forceinline__ u64 pack_dup(float x) {
    u64 r; asm("mov.b64 %0, {%1,%1};" : "=l"(r) : "f"(x)); return r;
}
__device__ __forceinline__ void fma2(u64& acc, u64 a, u64 b) {
    asm("fma.rn.f32x2 %0, %1, %2, %0;" : "+l"(acc) : "l"(a), "l"(b));
}
__device__ __forceinline__ float2 unpack2(u64 v) {
    float2 f; asm("mov.b64 {%0,%1}, %2;" : "=f"(f.x), "=f"(f.y) : "l"(v)); return f;
}
__device__ __forceinline__ void lds_v2u64(u64& a, u64& b, uint32_t addr) {
    asm("ld.shared.v2.b64 {%0,%1}, [%2];" : "=l"(a), "=l"(b) : "r"(addr));
}
__device__ __forceinline__ float2 lds_f2(uint32_t addr) {
    float2 v;
    asm("ld.shared.v2.f32 {%0,%1}, [%2];" : "=f"(v.x), "=f"(v.y) : "r"(addr));
    return v;
}

// acc2[16] (32 channels) += x[0..63] (smem, byte addr aAddr) @ W seg (smem byte addr wAddr,
// row-major 64 floats/row; wAddr already offset by half*32 channels).
// All lanes of a warp read the same W address -> pure broadcast LDS.
__device__ __forceinline__ void gemm_seg(u64* acc2, uint32_t aAddr, uint32_t wAddr)
{
    #pragma unroll 8
    for (int k2 = 0; k2 < 32; k2++) {
        float2 xv = lds_f2(aAddr + k2 * 8);
        u64 x0 = pack_dup(xv.x);
        u64 x1 = pack_dup(xv.y);
        uint32_t r0 = wAddr + (k2 * 2) * 256;
        uint32_t r1 = r0 + 256;
        #pragma unroll
        for (int j = 0; j < 8; j++) {
            u64 w0, w1;
            lds_v2u64(w0, w1, r0 + j * 16);
            fma2(acc2[2 * j],     x0, w0);
            fma2(acc2[2 * j + 1], x0, w1);
        }
        #pragma unroll
        for (int j = 0; j < 8; j++) {
            u64 w0, w1;
            lds_v2u64(w0, w1, r1 + j * 16);
            fma2(acc2[2 * j],     x1, w0);
            fma2(acc2[2 * j + 1], x1, w1);
        }
    }
}

// warp-cooperative neighbor mean for node g: returns this lane's float2 (channels 2*lane, 2*lane+1)
__device__ __forceinline__ float2 gather_mean(
    const float* __restrict__ src, const int* __restrict__ rs,
    const int* __restrict__ adj, const float* __restrict__ inv, int g, int lane)
{
    int start = __ldg(rs + g), end = __ldg(rs + g + 1);
    const float2* base = (const float2*)src;
    float ax = 0.f, ay = 0.f;
    int p = start;
    for (; p + 4 <= end; p += 4) {
        int j0 = __ldg(adj + p),     j1 = __ldg(adj + p + 1);
        int j2 = __ldg(adj + p + 2), j3 = __ldg(adj + p + 3);
        float2 v0 = __ldg(base + (size_t)j0 * 32 + lane);
        float2 v1 = __ldg(base + (size_t)j1 * 32 + lane);
        float2 v2 = __ldg(base + (size_t)j2 * 32 + lane);
        float2 v3 = __ldg(base + (size_t)j3 * 32 + lane);
        ax += (v0.x + v1.x) + (v2.x + v3.x);
        ay += (v0.y + v1.y) + (v2.y + v3.y);
    }
    for (; p < end; p++) {
        int j = __ldg(adj + p);
        float2 v = __ldg(base + (size_t)j * 32 + lane);
        ax += v.x; ay += v.y;
    }
    float iv = __ldg(inv + g);
    return make_float2(ax * iv, ay * iv);
}

// ---------------- 1) encoder + edge counting (fused) ----------------
__global__ void __launch_bounds__(128) encoder_kernel(
    const float* __restrict__ xl, const float* __restrict__ xc,
    const float* __restrict__ w1, const float* __restrict__ b1,
    const float* __restrict__ w2, const float* __restrict__ b2,
    const int* __restrict__ el, const int* __restrict__ ec,
    int* __restrict__ cnt,
    float* __restrict__ hl, float* __restrict__ hc)
{
    __shared__ __align__(16) float sW1[4 * CH];
    __shared__ __align__(16) float sb1[CH];
    __shared__ __align__(16) float sW2[CH * CH];
    __shared__ __align__(16) float sb2[CH];
    for (int t = threadIdx.x; t < 64; t += 128) ((float4*)sW1)[t] = ((const float4*)w1)[t];
    for (int t = threadIdx.x; t < CH * 16; t += 128) ((float4*)sW2)[t] = ((const float4*)w2)[t];
    if (threadIdx.x < CH) { sb1[threadIdx.x] = b1[threadIdx.x]; sb2[threadIdx.x] = b2[threadIdx.x]; }
    __syncthreads();
    uint32_t sw2a = (uint32_t)__cvta_generic_to_shared(sW2);

    int i = blockIdx.x * 128 + threadIdx.x;
    int stride = gridDim.x * 128;

    // fused edge degree counting (cnt zeroed by previous call's fill / static init)
    for (size_t e = i; e < NE; e += stride) {
        atomicAdd(cnt + __ldg(ec + e), 1);
        atomicAdd(cnt + N_CLS + __ldg(el + e), 1);
    }

    if (i >= NT) return;
    const float* x;
    float* out;
    if (i < N_LIT) { x = xl + (size_t)i * 4;           out = hl + (size_t)i * CH; }
    else           { x = xc + (size_t)(i - N_LIT) * 4; out = hc + (size_t)(i - N_LIT) * CH; }
    float4 xv = __ldg((const float4*)x);

    u64 acc2[32];
    #pragma unroll
    for (int j = 0; j < 16; j++) {
        float4 bv = ((const float4*)sb2)[j];
        acc2[2 * j]     = pack2(bv.x, bv.y);
        acc2[2 * j + 1] = pack2(bv.z, bv.w);
    }

    #pragma unroll 8
    for (int k = 0; k < CH; k++) {
        float t = sb1[k] + xv.x * sW1[k] + xv.y * sW1[CH + k] + xv.z * sW1[2 * CH + k] + xv.w * sW1[3 * CH + k];
        u64 s2 = pack_dup(silu(t));
        uint32_t ra = sw2a + (k << 8);
        #pragma unroll
        for (int j = 0; j < 16; j++) {
            u64 w0, w1v;
            lds_v2u64(w0, w1v, ra + (j << 4));
            fma2(acc2[2 * j],     s2, w0);
            fma2(acc2[2 * j + 1], s2, w1v);
        }
    }
    #pragma unroll
    for (int j = 0; j < 16; j++) {
        float2 a = unpack2(acc2[2 * j]);
        float2 b = unpack2(acc2[2 * j + 1]);
        ((float4*)out)[j] = make_float4(a.x, a.y, b.x, b.y);
    }
}

// ---------------- 2-4) concatenated scan over cnt[NT] ----------------
__global__ void reduce_block(const int* __restrict__ cnt, int* __restrict__ bsum, int n) {
    __shared__ int s[SCAN_B];
    int i = blockIdx.x * SCAN_B + threadIdx.x;
    s[threadIdx.x] = (i < n) ? cnt[i] : 0;
    __syncthreads();
    for (int off = 512; off > 0; off >>= 1) {
        if (threadIdx.x < off) s[threadIdx.x] += s[threadIdx.x + off];
        __syncthreads();
    }
    if (threadIdx.x == 0) bsum[blockIdx.x] = s[0];
}

__global__ void scan_sums(int* __restrict__ bsum, int nb) {
    __shared__ int s[SCAN_B];
    int v = (threadIdx.x < nb) ? bsum[threadIdx.x] : 0;
    s[threadIdx.x] = v; __syncthreads();
    for (int off = 1; off < SCAN_B; off <<= 1) {
        int t = (threadIdx.x >= off) ? s[threadIdx.x - off] : 0;
        __syncthreads();
        s[threadIdx.x] += t;
        __syncthreads();
    }
    if (threadIdx.x < nb) bsum[threadIdx.x] = s[threadIdx.x] - v;  // exclusive
}

__global__ void scan_apply(const int* __restrict__ cnt, const int* __restrict__ bsum,
                           int* __restrict__ rs, int* __restrict__ cur,
                           float* __restrict__ inv, int n) {
    __shared__ int s[SCAN_B];
    int i = blockIdx.x * SCAN_B + threadIdx.x;
    int v = (i < n) ? cnt[i] : 0;
    s[threadIdx.x] = v; __syncthreads();
    for (int off = 1; off < SCAN_B; off <<= 1) {
        int t = (threadIdx.x >= off) ? s[threadIdx.x - off] : 0;
        __syncthreads();
        s[threadIdx.x] += t;
        __syncthreads();
    }
    if (i < n) {
        int r = s[threadIdx.x] - v + bsum[blockIdx.x];
        rs[i] = r;
        cur[i] = r;
        inv[i] = (v > 0) ? (1.0f / (float)v) : 1.0f;
    }
    if (i == 0) rs[n] = 2 * NE;
}

// ---------------- 5) adjacency fill (+ re-zero cnt for next call) ----------------
__global__ void fill_kernel(const int* __restrict__ el, const int* __restrict__ ec,
                            int* __restrict__ cur, int* __restrict__ adj,
                            int* __restrict__ cnt) {
    int e = blockIdx.x * 256 + threadIdx.x;
    if (e < NT) cnt[e] = 0;
    if (e < NE) {
        int l = __ldg(el + e), c = __ldg(ec + e);
        adj[atomicAdd(cur + c, 1)]         = l;
        adj[atomicAdd(cur + N_CLS + l, 1)] = c;
    }
}

// ---------------- fused cls layer: gather(hl) + GEMM + silu -> hc ----------------
__global__ void __launch_bounds__(128) fused_cls(
    const float* __restrict__ hl, float* __restrict__ hc,
    const int* __restrict__ rs, const int* __restrict__ adj,
    const float* __restrict__ inv,
    const float* __restrict__ W, const float* __restrict__ b)
{
    extern __shared__ __align__(16) float smem[];
    float* sA = smem;                  // [64][130]
    float* sW = smem + NPB * ST;       // [128][64]
    float* sb = sW + 2 * CH * CH;      // [64]
    int tid = threadIdx.x;
    for (int t = tid; t < 2 * CH * 16; t += 128) ((float4*)sW)[t] = ((const float4*)W)[t];
    if (tid < CH) sb[tid] = b[tid];

    int warp = tid >> 5, lane = tid & 31;
    int gbase = blockIdx.x * NPB;
    #pragma unroll 1
    for (int i = 0; i < 16; i++) {
        int n = warp * 16 + i;
        int g = gbase + n;
        float2 sv = __ldg((const float2*)(hc + (size_t)g * CH) + lane);   // self
        float2 mv = gather_mean(hl, rs, adj, inv, g, lane);               // mean msg
        float* row = sA + n * ST;
        ((float2*)row)[lane] = sv;
        ((float2*)(row + CH))[lane] = mv;
    }
    __syncthreads();

    // GEMM: half = tid>>6 so W reads are warp-uniform broadcast
    int n = tid & 63, half = tid >> 6;
    uint32_t aAddr = (uint32_t)__cvta_generic_to_shared(sA + n * ST);
    uint32_t wAddr = (uint32_t)__cvta_generic_to_shared(sW) + half * 128;

    u64 acc2[16];
    #pragma unroll
    for (int j = 0; j < 8; j++) {
        float4 bv = ((const float4*)(sb + half * 32))[j / 2 * 2 + (j & 1)];
        acc2[2 * j]     = pack2(bv.x, bv.y);
        acc2[2 * j + 1] = pack2(bv.z, bv.w);
    }

    gemm_seg(acc2, aAddr,          wAddr);                 // self @ W[0:64]
    gemm_seg(acc2, aAddr + CH * 4, wAddr + CH * CH * 4);   // msg  @ W[64:128]

    float* out = hc + (size_t)(gbase + n) * CH + half * 32;
    #pragma unroll
    for (int j = 0; j < 8; j++) {
        float2 a = unpack2(acc2[2 * j]);
        float2 c = unpack2(acc2[2 * j + 1]);
        ((float4*)out)[j] = make_float4(silu(a.x), silu(a.y), silu(c.x), silu(c.y));
    }
}

// ---------------- fused lit layer: gather(hc) + GEMM(+flip from smem) -> hdst ----------------
__global__ void __launch_bounds__(128) fused_lit(
    const float* __restrict__ hc, const float* __restrict__ hsrc,
    float* __restrict__ hdst,
    const int* __restrict__ rs, const int* __restrict__ adj,
    const float* __restrict__ inv,
    const float* __restrict__ W, const float* __restrict__ b)
{
    extern __shared__ __align__(16) float smem[];
    float* sA = smem;                  // [64][130]
    float* sW = smem + NPB * ST;       // [192][64]
    float* sb = sW + 3 * CH * CH;      // [64]
    int tid = threadIdx.x;
    for (int t = tid; t < 3 * CH * 16; t += 128) ((float4*)sW)[t] = ((const float4*)W)[t];
    if (tid < CH) sb[tid] = b[tid];

    int warp = tid >> 5, lane = tid & 31;
    int gbase = blockIdx.x * NPB;
    #pragma unroll 1
    for (int i = 0; i < 16; i++) {
        int n = warp * 16 + i;
        int g = gbase + n;
        float2 sv = __ldg((const float2*)(hsrc + (size_t)g * CH) + lane);  // self
        float2 mv = gather_mean(hc, rs, adj, inv, g, lane);                // mean msg
        float* row = sA + n * ST;
        ((float2*)row)[lane] = sv;
        ((float2*)(row + CH))[lane] = mv;
    }
    __syncthreads();

    int n = tid & 63, half = tid >> 6;
    uint32_t sA0   = (uint32_t)__cvta_generic_to_shared(sA);
    uint32_t aAddr = sA0 + n * (ST * 4);
    uint32_t fAddr = sA0 + (n ^ 1) * (ST * 4);   // negated literal's self row (in tile)
    uint32_t wAddr = (uint32_t)__cvta_generic_to_shared(sW) + half * 128;

    u64 acc2[16];
    #pragma unroll
    for (int j = 0; j < 8; j++) {
        float4 bv = ((const float4*)(sb + half * 32))[j / 2 * 2 + (j & 1)];
        acc2[2 * j]     = pack2(bv.x, bv.y);
        acc2[2 * j + 1] = pack2(bv.z, bv.w);
    }

    gemm_seg(acc2, aAddr,          wAddr);                     // self @ W[0:64]
    gemm_seg(acc2, aAddr + CH * 4, wAddr + CH * CH * 4);       // msg  @ W[64:128]
    gemm_seg(acc2, fAddr,          wAddr + 2 * CH * CH * 4);   // flip @ W[128:192]

    float* out = hdst + (size_t)(gbase + n) * CH + half * 32;
    #pragma unroll
    for (int j = 0; j < 8; j++) {
        float2 a = unpack2(acc2[2 * j]);
        float2 c = unpack2(acc2[2 * j + 1]);
        ((float4*)out)[j] = make_float4(silu(a.x), silu(a.y), silu(c.x), silu(c.y));
    }
}

// ---------------- readout ----------------
#define W1T_STRIDE 132   // floats; 528B, 16B-aligned
__global__ void __launch_bounds__(128) readout_kernel(
    const float* __restrict__ hl,
    const float* __restrict__ w1, const float* __restrict__ b1,
    const float* __restrict__ w2, const float* __restrict__ b2,
    float* __restrict__ out)
{
    extern __shared__ __align__(16) float smem[];
    float* sW1T = smem;                       // [128][132] transposed, padded
    float* sb1  = smem + 128 * W1T_STRIDE;
    float* sW2  = sb1 + 128;
    float* sb2  = sW2 + 256;
    for (int t = threadIdx.x; t < 128 * 128; t += 128) {
        int i = t >> 7, k = t & 127;
        sW1T[k * W1T_STRIDE + i] = w1[t];     // w1[i][k]
    }
    sb1[threadIdx.x] = b1[threadIdx.x];
    for (int t = threadIdx.x; t < 256; t += 128) sW2[t] = w2[t];
    if (threadIdx.x < 2) sb2[threadIdx.x] = b2[threadIdx.x];
    __syncthreads();
    uint32_t swa = (uint32_t)__cvta_generic_to_shared(sW1T);

    int v = blockIdx.x * 128 + threadIdx.x;
    if (v >= NVAR) return;

    u64 hv2[64];
    const float4* hp = (const float4*)(hl + (size_t)v * 128);
    #pragma unroll
    for (int j = 0; j < 32; j++) {
        float4 h = __ldg(hp + j);
        hv2[2 * j]     = pack2(h.x, h.y);
        hv2[2 * j + 1] = pack2(h.z, h.w);
    }

    float y0 = sb2[0], y1 = sb2[1];
    #pragma unroll 2
    for (int k = 0; k < 128; k++) {
        u64 t0 = 0, t1 = 0, t2 = 0, t3 = 0;
        uint32_t ra = swa + k * (W1T_STRIDE * 4);
        #pragma unroll
        for (int j = 0; j < 32; j++) {
            u64 w0, w1v;
            lds_v2u64(w0, w1v, ra + (j << 4));
            fma2((j & 1) ? t1 : t0, hv2[2 * j],     w0);
            fma2((j & 1) ? t3 : t2, hv2[2 * j + 1], w1v);
        }
        float2 a = unpack2(t0), bq = unpack2(t1), c = unpack2(t2), d = unpack2(t3);
        float t = ((a.x + a.y) + (bq.x + bq.y)) + ((c.x + c.y) + (d.x + d.y)) + sb1[k];
        float s = silu(t);
        y0 += s * sW2[2 * k];
        y1 += s * sW2[2 * k + 1];
    }
    out[2 * v]     = y0;
    out[2 * v + 1] = y1;
}

// ---------------- launcher ----------------
extern "C" void kernel_launch(void* const* d_in, const int* in_sizes, int n_in,
                              void* d_out, int out_size)
{
    const float* x_lit  = (const float*)d_in[0];
    const float* x_cls  = (const float*)d_in[1];
    const int*   e_lit  = (const int*)  d_in[2];
    const int*   e_cls  = (const int*)  d_in[3];
    const float* enc_w1 = (const float*)d_in[4];
    const float* enc_b1 = (const float*)d_in[5];
    const float* enc_w2 = (const float*)d_in[6];
    const float* enc_b2 = (const float*)d_in[7];
    const float* Wc     = (const float*)d_in[8];
    const float* bc     = (const float*)d_in[9];
    const float* Wl     = (const float*)d_in[10];
    const float* bl     = (const float*)d_in[11];
    const float* out_w1 = (const float*)d_in[12];
    const float* out_b1 = (const float*)d_in[13];
    const float* out_w2 = (const float*)d_in[14];
    const float* out_b2 = (const float*)d_in[15];
    float* y = (float*)d_out;

    float *p_hlA, *p_hlB, *p_hc, *p_inv;
    int *p_cnt, *p_rs, *p_cur, *p_adj, *p_bsum;
    cudaGetSymbolAddress((void**)&p_hlA, g_hlA);
    cudaGetSymbolAddress((void**)&p_hlB, g_hlB);
    cudaGetSymbolAddress((void**)&p_hc,  g_hc);
    cudaGetSymbolAddress((void**)&p_cnt, g_cnt);
    cudaGetSymbolAddress((void**)&p_inv, g_inv);
    cudaGetSymbolAddress((void**)&p_rs,  g_rs);
    cudaGetSymbolAddress((void**)&p_cur, g_cur);
    cudaGetSymbolAddress((void**)&p_adj, g_adj);
    cudaGetSymbolAddress((void**)&p_bsum, g_bsum);

    const int smem_cls = (NPB * ST + 2 * CH * CH + CH) * 4;   // 66304 B
    const int smem_lit = (NPB * ST + 3 * CH * CH + CH) * 4;   // 82688 B
    cudaFuncSetAttribute(fused_cls, cudaFuncAttributeMaxDynamicSharedMemorySize, smem_cls);
    cudaFuncSetAttribute(fused_lit, cudaFuncAttributeMaxDynamicSharedMemorySize, smem_lit);
    cudaFuncSetAttribute(readout_kernel, cudaFuncAttributeMaxDynamicSharedMemorySize,
                         (128 * W1T_STRIDE + 128 + 256 + 8) * 4);

    // 1) encoder + edge counting
    encoder_kernel<<<(NT + 127) / 128, 128>>>(
        x_lit, x_cls, enc_w1, enc_b1, enc_w2, enc_b2,
        e_lit, e_cls, p_cnt, p_hlA, p_hc);

    // 2-4) scan over concatenated counts -> row starts, cur, inv
    int nb = (NT + SCAN_B - 1) / SCAN_B;   // 977
    reduce_block<<<nb, SCAN_B>>>(p_cnt, p_bsum, NT);
    scan_sums<<<1, SCAN_B>>>(p_bsum, nb);
    scan_apply<<<nb, SCAN_B>>>(p_cnt, p_bsum, p_rs, p_cur, p_inv, NT);

    // 5) adjacency fill + re-zero cnt
    fill_kernel<<<(NE + 255) / 256, 256>>>(e_lit, e_cls, p_cur, p_adj, p_cnt);

    // 6+) fused message-passing layers
    float* cur = p_hlA;
    float* nxt = p_hlB;
    for (int l = 0; l < NLAY; l++) {
        fused_cls<<<N_CLS / NPB, 128, smem_cls>>>(
            cur, p_hc, p_rs, p_adj, p_inv,
            Wc + (size_t)l * 2 * CH * CH, bc + l * CH);
        fused_lit<<<N_LIT / NPB, 128, smem_lit>>>(
            p_hc, cur, nxt, p_rs + N_CLS, p_adj, p_inv + N_CLS,
            Wl + (size_t)l * 3 * CH * CH, bl + l * CH);
        float* tmp = cur; cur = nxt; nxt = tmp;
    }

    // readout
    readout_kernel<<<(NVAR + 127) / 128, 128, (128 * W1T_STRIDE + 128 + 256 + 8) * 4>>>(
        cur, out_w1, out_b1, out_w2, out_b2, y);
}

// round 6
// speedup vs baseline: 1.4793x; 1.4793x over previous
#include <cuda_runtime.h>
#include <cuda_bf16.h>
#include <cstddef>
#include <cstdint>

#define N_LIT 200000
#define N_CLS 800000
#define NE    2400000
#define NT    (N_CLS + N_LIT)
#define CH    64
#define NVAR  (N_LIT/2)
#define NLAY  4
#define SCAN_B 1024

typedef unsigned long long u64;

// ---------------- device scratch (static, no allocation) ----------------
__device__ float g_hlA[(size_t)N_LIT * CH];
__device__ float g_hlB[(size_t)N_LIT * CH];
__device__ float g_hc [(size_t)N_CLS * CH];
__device__ float g_m  [(size_t)N_CLS * CH];
__device__ int   g_cnt[NT];          // zero-init; re-zeroed by fill_kernel each call
__device__ float g_inv[NT];
__device__ int   g_rs [NT + 1];
__device__ int   g_cur[NT];
__device__ int   g_adj[2 * NE];      // [0,NE): lits by clause; [NE,2NE): clauses by literal
__device__ u64   g_tiles[1024];      // decoupled-lookback state: (flag<<32)|value
__device__ unsigned int g_ctr;       // ticket counter

__device__ __forceinline__ float silu(float x) { return x / (1.0f + __expf(-x)); }

// ---- f32x2 packed helpers (FFMA2 path, sm_100+) ----
__device__ __forceinline__ u64 pack2(float lo, float hi) {
    u64 r; asm("mov.b64 %0, {%1,%2};" : "=l"(r) : "f"(lo), "f"(hi)); return r;
}
__device__ __forceinline__ u64 pack_dup(float x) {
    u64 r; asm("mov.b64 %0, {%1,%1};" : "=l"(r) : "f"(x)); return r;
}
__device__ __forceinline__ void fma2(u64& acc, u64 a, u64 b) {
    asm("fma.rn.f32x2 %0, %1, %2, %0;" : "+l"(acc) : "l"(a), "l"(b));
}
__device__ __forceinline__ float2 unpack2(u64 v) {
    float2 f; asm("mov.b64 {%0,%1}, %2;" : "=f"(f.x), "=f"(f.y) : "l"(v)); return f;
}
__device__ __forceinline__ void lds_v2u64(u64& a, u64& b, uint32_t addr) {
    asm("ld.shared.v2.b64 {%0,%1}, [%2];" : "=l"(a), "=l"(b) : "r"(addr));
}

// acc2[32] += x_row[0..63] (gmem, LDG.128) @ W_block (smem byte addr sw, row-major 64 wide)
__device__ __forceinline__ void gemm_v(u64* acc2, const float* __restrict__ x, uint32_t sw)
{
    #pragma unroll
    for (int kk = 0; kk < 4; kk++) {
        float4 xv0 = __ldg((const float4*)x + kk * 4 + 0);
        float4 xv1 = __ldg((const float4*)x + kk * 4 + 1);
        float4 xv2 = __ldg((const float4*)x + kk * 4 + 2);
        float4 xv3 = __ldg((const float4*)x + kk * 4 + 3);
        float xs[16] = {xv0.x, xv0.y, xv0.z, xv0.w,
                        xv1.x, xv1.y, xv1.z, xv1.w,
                        xv2.x, xv2.y, xv2.z, xv2.w,
                        xv3.x, xv3.y, xv3.z, xv3.w};
        #pragma unroll
        for (int e = 0; e < 16; e++) {
            u64 xk2 = pack_dup(xs[e]);
            uint32_t ra = sw + ((kk * 16 + e) << 8);
            #pragma unroll
            for (int j = 0; j < 16; j++) {
                u64 w0, w1;
                lds_v2u64(w0, w1, ra + (j << 4));
                fma2(acc2[2 * j],     xk2, w0);
                fma2(acc2[2 * j + 1], xk2, w1);
            }
        }
    }
}

// ---------------- 1) encoder + edge counting (fused) ----------------
__global__ void __launch_bounds__(128) encoder_kernel(
    const float* __restrict__ xl, const float* __restrict__ xc,
    const float* __restrict__ w1, const float* __restrict__ b1,
    const float* __restrict__ w2, const float* __restrict__ b2,
    const int* __restrict__ el, const int* __restrict__ ec,
    int* __restrict__ cnt,
    float* __restrict__ hl, float* __restrict__ hc)
{
    __shared__ __align__(16) float sW1[4 * CH];
    __shared__ __align__(16) float sb1[CH];
    __shared__ __align__(16) float sW2[CH * CH];
    __shared__ __align__(16) float sb2[CH];
    for (int t = threadIdx.x; t < 64; t += 128) ((float4*)sW1)[t] = ((const float4*)w1)[t];
    for (int t = threadIdx.x; t < CH * 16; t += 128) ((float4*)sW2)[t] = ((const float4*)w2)[t];
    if (threadIdx.x < CH) { sb1[threadIdx.x] = b1[threadIdx.x]; sb2[threadIdx.x] = b2[threadIdx.x]; }
    __syncthreads();
    uint32_t sw2a = (uint32_t)__cvta_generic_to_shared(sW2);

    int i = blockIdx.x * 128 + threadIdx.x;
    int stride = gridDim.x * 128;

    for (size_t e = i; e < NE; e += stride) {
        atomicAdd(cnt + __ldg(ec + e), 1);
        atomicAdd(cnt + N_CLS + __ldg(el + e), 1);
    }

    if (i >= NT) return;
    const float* x;
    float* out;
    if (i < N_LIT) { x = xl + (size_t)i * 4;           out = hl + (size_t)i * CH; }
    else           { x = xc + (size_t)(i - N_LIT) * 4; out = hc + (size_t)(i - N_LIT) * CH; }
    float4 xv = __ldg((const float4*)x);

    u64 acc2[32];
    #pragma unroll
    for (int j = 0; j < 16; j++) {
        float4 bv = ((const float4*)sb2)[j];
        acc2[2 * j]     = pack2(bv.x, bv.y);
        acc2[2 * j + 1] = pack2(bv.z, bv.w);
    }

    #pragma unroll 8
    for (int k = 0; k < CH; k++) {
        float t = sb1[k] + xv.x * sW1[k] + xv.y * sW1[CH + k] + xv.z * sW1[2 * CH + k] + xv.w * sW1[3 * CH + k];
        u64 s2 = pack_dup(silu(t));
        uint32_t ra = sw2a + (k << 8);
        #pragma unroll
        for (int j = 0; j < 16; j++) {
            u64 w0, w1v;
            lds_v2u64(w0, w1v, ra + (j << 4));
            fma2(acc2[2 * j],     s2, w0);
            fma2(acc2[2 * j + 1], s2, w1v);
        }
    }
    #pragma unroll
    for (int j = 0; j < 16; j++) {
        float2 a = unpack2(acc2[2 * j]);
        float2 b = unpack2(acc2[2 * j + 1]);
        ((float4*)out)[j] = make_float4(a.x, a.y, b.x, b.y);
    }
}

// ---------------- 2) single-pass scan (decoupled lookback, ticket-ordered) ----------------
__global__ void __launch_bounds__(SCAN_B) scan_onepass(
    const int* __restrict__ cnt, int* __restrict__ rs, int* __restrict__ cur,
    float* __restrict__ inv, int n)
{
    __shared__ int s[SCAN_B];
    __shared__ int sbid;
    __shared__ int sbase;
    if (threadIdx.x == 0) sbid = (int)atomicAdd(&g_ctr, 1u);
    __syncthreads();
    int bid = sbid;
    int i = bid * SCAN_B + threadIdx.x;
    int v = (i < n) ? cnt[i] : 0;
    s[threadIdx.x] = v;
    __syncthreads();
    for (int off = 1; off < SCAN_B; off <<= 1) {
        int t = (threadIdx.x >= off) ? s[threadIdx.x - off] : 0;
        __syncthreads();
        s[threadIdx.x] += t;
        __syncthreads();
    }
    if (threadIdx.x == 0) {
        int total = s[SCAN_B - 1];
        if (bid == 0) {
            atomicExch(&g_tiles[0], (2ull << 32) | (unsigned)total);
            sbase = 0;
        } else {
            atomicExch(&g_tiles[bid], (1ull << 32) | (unsigned)total);
            int base = 0;
            int t = bid - 1;
            while (t >= 0) {
                u64 st;
                do { st = atomicAdd(&g_tiles[t], 0ull); } while ((st >> 32) == 0ull);
                base += (int)(unsigned)st;
                if ((st >> 32) == 2ull) break;
                t--;
            }
            atomicExch(&g_tiles[bid], (2ull << 32) | (unsigned)(base + total));
            sbase = base;
        }
    }
    __syncthreads();
    int base = sbase;
    if (i < n) {
        int r = base + s[threadIdx.x] - v;
        rs[i] = r;
        cur[i] = r;
        inv[i] = (v > 0) ? (1.0f / (float)v) : 1.0f;
    }
    if (bid == 0 && threadIdx.x == 0) rs[n] = 2 * NE;
}

// ---------------- 3) adjacency fill (+ reset cnt / scan state for next call) ----------------
__global__ void fill_kernel(const int* __restrict__ el, const int* __restrict__ ec,
                            int* __restrict__ cur, int* __restrict__ adj,
                            int* __restrict__ cnt) {
    int e = blockIdx.x * 256 + threadIdx.x;
    if (e < NT) cnt[e] = 0;
    if (e < 1024) g_tiles[e] = 0ull;
    if (e == 0) g_ctr = 0u;
    if (e < NE) {
        int l = __ldg(el + e), c = __ldg(ec + e);
        adj[atomicAdd(cur + c, 1)]         = l;
        adj[atomicAdd(cur + N_CLS + l, 1)] = c;
    }
}

// ---------------- aggregation: warp-per-node, coalesced adj + shfl broadcast ----------------
__global__ void __launch_bounds__(256) agg_kernel(
    const float* __restrict__ src, const int* __restrict__ rs,
    const int* __restrict__ adj, const float* __restrict__ inv,
    float* __restrict__ m, int n)
{
    int w = (blockIdx.x * 256 + threadIdx.x) >> 5;
    if (w >= n) return;
    int lane = threadIdx.x & 31;
    int start = __ldg(rs + w), end = __ldg(rs + w + 1);
    const float2* base = (const float2*)src;
    float ax = 0.f, ay = 0.f;
    for (int p0 = start; p0 < end; p0 += 32) {
        int idx = p0 + lane;
        int a = (idx < end) ? __ldg(adj + idx) : 0;   // one coalesced load per 32 neighbors
        int mc = min(32, end - p0);
        int t = 0;
        for (; t + 4 <= mc; t += 4) {
            int j0 = __shfl_sync(0xffffffffu, a, t);
            int j1 = __shfl_sync(0xffffffffu, a, t + 1);
            int j2 = __shfl_sync(0xffffffffu, a, t + 2);
            int j3 = __shfl_sync(0xffffffffu, a, t + 3);
            float2 v0 = __ldg(base + (size_t)j0 * 32 + lane);
            float2 v1 = __ldg(base + (size_t)j1 * 32 + lane);
            float2 v2 = __ldg(base + (size_t)j2 * 32 + lane);
            float2 v3 = __ldg(base + (size_t)j3 * 32 + lane);
            ax += (v0.x + v1.x) + (v2.x + v3.x);
            ay += (v0.y + v1.y) + (v2.y + v3.y);
        }
        for (; t < mc; t++) {
            int j = __shfl_sync(0xffffffffu, a, t);
            float2 v = __ldg(base + (size_t)j * 32 + lane);
            ax += v.x; ay += v.y;
        }
    }
    float iv = __ldg(inv + w);
    ((float2*)m)[(size_t)w * 32 + lane] = make_float2(ax * iv, ay * iv);
}

// ---------------- cls update: hc = silu([hc, m] @ Wc + bc) in place ----------------
__global__ void __launch_bounds__(128) cls_update(
    float* __restrict__ hc, const float* __restrict__ m,
    const float* __restrict__ W, const float* __restrict__ b)
{
    __shared__ __align__(16) float sW[2 * CH * CH];
    __shared__ __align__(16) float sb[CH];
    for (int t = threadIdx.x; t < 2 * CH * 16; t += 128) ((float4*)sW)[t] = ((const float4*)W)[t];
    if (threadIdx.x < CH) sb[threadIdx.x] = b[threadIdx.x];
    __syncthreads();
    uint32_t swa = (uint32_t)__cvta_generic_to_shared(sW);

    size_t i = (size_t)blockIdx.x * 128 + threadIdx.x;
    if (i >= N_CLS) return;

    u64 acc2[32];
    #pragma unroll
    for (int j = 0; j < 16; j++) {
        float4 bv = ((const float4*)sb)[j];
        acc2[2 * j]     = pack2(bv.x, bv.y);
        acc2[2 * j + 1] = pack2(bv.z, bv.w);
    }

    gemm_v(acc2, hc + i * CH, swa);
    gemm_v(acc2, m  + i * CH, swa + CH * CH * 4);

    float* row = hc + i * CH;
    #pragma unroll
    for (int j = 0; j < 16; j++) {
        float2 a = unpack2(acc2[2 * j]);
        float2 c = unpack2(acc2[2 * j + 1]);
        ((float4*)row)[j] = make_float4(silu(a.x), silu(a.y), silu(c.x), silu(c.y));
    }
}

// ---------------- lit update: hdst = silu([hsrc, m, hsrc_flip] @ Wl + bl) ----------------
__global__ void __launch_bounds__(128) lit_update(
    const float* __restrict__ hsrc, float* __restrict__ hdst,
    const float* __restrict__ m,
    const float* __restrict__ W, const float* __restrict__ b)
{
    extern __shared__ __align__(16) float smem[];
    float* sW = smem;                    // 192*64 floats = 48KB
    float* sb = smem + 3 * CH * CH;
    for (int t = threadIdx.x; t < 3 * CH * 16; t += 128) ((float4*)sW)[t] = ((const float4*)W)[t];
    if (threadIdx.x < CH) sb[threadIdx.x] = b[threadIdx.x];
    __syncthreads();
    uint32_t swa = (uint32_t)__cvta_generic_to_shared(sW);

    size_t i = (size_t)blockIdx.x * 128 + threadIdx.x;
    if (i >= N_LIT) return;

    u64 acc2[32];
    #pragma unroll
    for (int j = 0; j < 16; j++) {
        float4 bv = ((const float4*)sb)[j];
        acc2[2 * j]     = pack2(bv.x, bv.y);
        acc2[2 * j + 1] = pack2(bv.z, bv.w);
    }

    gemm_v(acc2, hsrc + i * CH,       swa);
    gemm_v(acc2, m    + i * CH,       swa + CH * CH * 4);
    gemm_v(acc2, hsrc + (i ^ 1) * CH, swa + 2 * CH * CH * 4);

    float* out = hdst + i * CH;
    #pragma unroll
    for (int j = 0; j < 16; j++) {
        float2 a = unpack2(acc2[2 * j]);
        float2 c = unpack2(acc2[2 * j + 1]);
        ((float4*)out)[j] = make_float4(silu(a.x), silu(a.y), silu(c.x), silu(c.y));
    }
}

// ---------------- readout ----------------
#define W1T_STRIDE 132   // floats; 528B, 16B-aligned
__global__ void __launch_bounds__(128) readout_kernel(
    const float* __restrict__ hl,
    const float* __restrict__ w1, const float* __restrict__ b1,
    const float* __restrict__ w2, const float* __restrict__ b2,
    float* __restrict__ out)
{
    extern __shared__ __align__(16) float smem[];
    float* sW1T = smem;                       // [128][132] transposed, padded
    float* sb1  = smem + 128 * W1T_STRIDE;
    float* sW2  = sb1 + 128;
    float* sb2  = sW2 + 256;
    for (int t = threadIdx.x; t < 128 * 128; t += 128) {
        int i = t >> 7, k = t & 127;
        sW1T[k * W1T_STRIDE + i] = w1[t];     // w1[i][k]
    }
    sb1[threadIdx.x] = b1[threadIdx.x];
    for (int t = threadIdx.x; t < 256; t += 128) sW2[t] = w2[t];
    if (threadIdx.x < 2) sb2[threadIdx.x] = b2[threadIdx.x];
    __syncthreads();
    uint32_t swa = (uint32_t)__cvta_generic_to_shared(sW1T);

    int v = blockIdx.x * 128 + threadIdx.x;
    if (v >= NVAR) return;

    u64 hv2[64];
    const float4* hp = (const float4*)(hl + (size_t)v * 128);
    #pragma unroll
    for (int j = 0; j < 32; j++) {
        float4 h = __ldg(hp + j);
        hv2[2 * j]     = pack2(h.x, h.y);
        hv2[2 * j + 1] = pack2(h.z, h.w);
    }

    float y0 = sb2[0], y1 = sb2[1];
    #pragma unroll 2
    for (int k = 0; k < 128; k++) {
        u64 t0 = 0, t1 = 0, t2 = 0, t3 = 0;
        uint32_t ra = swa + k * (W1T_STRIDE * 4);
        #pragma unroll
        for (int j = 0; j < 32; j++) {
            u64 w0, w1v;
            lds_v2u64(w0, w1v, ra + (j << 4));
            fma2((j & 1) ? t1 : t0, hv2[2 * j],     w0);
            fma2((j & 1) ? t3 : t2, hv2[2 * j + 1], w1v);
        }
        float2 a = unpack2(t0), bq = unpack2(t1), c = unpack2(t2), d = unpack2(t3);
        float t = ((a.x + a.y) + (bq.x + bq.y)) + ((c.x + c.y) + (d.x + d.y)) + sb1[k];
        float s = silu(t);
        y0 += s * sW2[2 * k];
        y1 += s * sW2[2 * k + 1];
    }
    out[2 * v]     = y0;
    out[2 * v + 1] = y1;
}

// ---------------- launcher ----------------
extern "C" void kernel_launch(void* const* d_in, const int* in_sizes, int n_in,
                              void* d_out, int out_size)
{
    const float* x_lit  = (const float*)d_in[0];
    const float* x_cls  = (const float*)d_in[1];
    const int*   e_lit  = (const int*)  d_in[2];
    const int*   e_cls  = (const int*)  d_in[3];
    const float* enc_w1 = (const float*)d_in[4];
    const float* enc_b1 = (const float*)d_in[5];
    const float* enc_w2 = (const float*)d_in[6];
    const float* enc_b2 = (const float*)d_in[7];
    const float* Wc     = (const float*)d_in[8];
    const float* bc     = (const float*)d_in[9];
    const float* Wl     = (const float*)d_in[10];
    const float* bl     = (const float*)d_in[11];
    const float* out_w1 = (const float*)d_in[12];
    const float* out_b1 = (const float*)d_in[13];
    const float* out_w2 = (const float*)d_in[14];
    const float* out_b2 = (const float*)d_in[15];
    float* y = (float*)d_out;

    float *p_hlA, *p_hlB, *p_hc, *p_m, *p_inv;
    int *p_cnt, *p_rs, *p_cur, *p_adj;
    cudaGetSymbolAddress((void**)&p_hlA, g_hlA);
    cudaGetSymbolAddress((void**)&p_hlB, g_hlB);
    cudaGetSymbolAddress((void**)&p_hc,  g_hc);
    cudaGetSymbolAddress((void**)&p_m,   g_m);
    cudaGetSymbolAddress((void**)&p_cnt, g_cnt);
    cudaGetSymbolAddress((void**)&p_inv, g_inv);
    cudaGetSymbolAddress((void**)&p_rs,  g_rs);
    cudaGetSymbolAddress((void**)&p_cur, g_cur);
    cudaGetSymbolAddress((void**)&p_adj, g_adj);

    cudaFuncSetAttribute(lit_update, cudaFuncAttributeMaxDynamicSharedMemorySize,
                         (3 * CH * CH + CH) * 4);
    cudaFuncSetAttribute(readout_kernel, cudaFuncAttributeMaxDynamicSharedMemorySize,
                         (128 * W1T_STRIDE + 128 + 256 + 8) * 4);

    // 1) encoder + edge counting (cnt/tiles/ctr reset by previous call's fill / static init)
    encoder_kernel<<<(NT + 127) / 128, 128>>>(
        x_lit, x_cls, enc_w1, enc_b1, enc_w2, enc_b2,
        e_lit, e_cls, p_cnt, p_hlA, p_hc);

    // 2) single-pass scan -> rs, cur, inv
    int nb = (NT + SCAN_B - 1) / SCAN_B;   // 977
    scan_onepass<<<nb, SCAN_B>>>(p_cnt, p_rs, p_cur, p_inv, NT);

    // 3) adjacency fill + reset cnt/scan state
    fill_kernel<<<(NE + 255) / 256, 256>>>(e_lit, e_cls, p_cur, p_adj, p_cnt);

    // 4+) message-passing layers (agg_cls is launch #4 -> ncu profile slot)
    float* cur = p_hlA;
    float* nxt = p_hlB;
    for (int l = 0; l < NLAY; l++) {
        agg_kernel<<<((size_t)N_CLS * 32 + 255) / 256, 256>>>(
            cur, p_rs, p_adj, p_inv, p_m, N_CLS);
        cls_update<<<(N_CLS + 127) / 128, 128>>>(
            p_hc, p_m, Wc + (size_t)l * 2 * CH * CH, bc + l * CH);
        agg_kernel<<<((size_t)N_LIT * 32 + 255) / 256, 256>>>(
            p_hc, p_rs + N_CLS, p_adj, p_inv + N_CLS, p_m, N_LIT);
        lit_update<<<(N_LIT + 127) / 128, 128, (3 * CH * CH + CH) * 4>>>(
            cur, nxt, p_m, Wl + (size_t)l * 3 * CH * CH, bl + l * CH);
        float* tmp = cur; cur = nxt; nxt = tmp;
    }

    // readout
    readout_kernel<<<(NVAR + 127) / 128, 128, (128 * W1T_STRIDE + 128 + 256 + 8) * 4>>>(
        cur, out_w1, out_b1, out_w2, out_b2, y);
}